// round 16
// baseline (speedup 1.0000x reference)
#include <cuda_runtime.h>
#include <cstdint>

// Problem constants (fixed by the reference: x is [2, B, N] fp32)
#define N_COLS 1024
#define B_ROWS 32768
#define THREADS 256
#define ROWS_PER_BLOCK 16
#define COLS_PER_THREAD (N_COLS / THREADS)   // 4

// Precomposed per-output-column tables (batch-independent):
//   g_idx[j] = (lp[rp[j]], lp[pp[rp[j]]])
//   g_w[j]   = (diag_r[k], diag_i[k], off_r[m], off_i[m]) with k=rp[j], m=pp[k]
__device__ int2   g_idx[N_COLS];
__device__ float4 g_w[N_COLS];

__global__ void prep_kernel(const int* __restrict__ pp,
                            const int* __restrict__ lp,
                            const int* __restrict__ rp,
                            const float* __restrict__ diag,      // [2, N]
                            const float* __restrict__ off_diag)  // [2, N]
{
    int j = threadIdx.x;            // 1024 threads, one per output column
    int k = rp[j];
    int m = pp[k];
    g_idx[j] = make_int2(lp[k], lp[m]);
    g_w[j]   = make_float4(diag[k], diag[N_COLS + k],
                           off_diag[m], off_diag[N_COLS + m]);
}

__global__ void __launch_bounds__(THREADS, 7)
mesh_kernel(const float* __restrict__ x, float* __restrict__ out)
{
    __shared__ int2   s_idx[N_COLS];   // 8 KB
    __shared__ float4 s_w[N_COLS];     // 16 KB
    __shared__ float2 s_x[N_COLS];     // 8 KB (re/im interleaved for one row)

    const int t = threadIdx.x;

    // Load the composed table once per block (hits L2 after first wave).
    #pragma unroll
    for (int i = 0; i < COLS_PER_THREAD; ++i) {
        int c = t + THREADS * i;
        s_idx[c] = g_idx[c];
        s_w[c]   = g_w[c];
    }

    const float* __restrict__ xr = x;                               // [B, N]
    const float* __restrict__ xi = x + (size_t)B_ROWS * N_COLS;
    float* __restrict__ outr = out;
    float* __restrict__ outi = out + (size_t)B_ROWS * N_COLS;

    const int row0 = blockIdx.x * ROWS_PER_BLOCK;
    __syncthreads();

    for (int r = 0; r < ROWS_PER_BLOCK; ++r) {
        const size_t base = (size_t)(row0 + r) * N_COLS;

        // Coalesced stage of one row (real+imag) into shared memory.
        // float2 STS at stride-256 columns: lanes hit distinct bank pairs.
        #pragma unroll
        for (int i = 0; i < COLS_PER_THREAD; ++i) {
            int c = t + THREADS * i;
            s_x[c] = make_float2(xr[base + c], xi[base + c]);
        }
        __syncthreads();

        // Gather from SMEM, complex MAC, coalesced 4B stores.
        #pragma unroll
        for (int i = 0; i < COLS_PER_THREAD; ++i) {
            int j = t + THREADS * i;
            int2   id = s_idx[j];
            float4 w  = s_w[j];
            float2 a  = s_x[id.x];   // o[k]   = x[lp[k]]
            float2 c2 = s_x[id.y];   // o[m]   = x[lp[m]]
            float vr = a.x * w.x - a.y * w.y + c2.x * w.z - c2.y * w.w;
            float vi = a.x * w.y + a.y * w.x + c2.x * w.w + c2.y * w.z;
            outr[base + j] = vr;
            outi[base + j] = vi;
        }
        __syncthreads();   // protect s_x before next row's stage
    }
}

extern "C" void kernel_launch(void* const* d_in, const int* in_sizes, int n_in,
                              void* d_out, int out_size)
{
    const float* x        = (const float*)d_in[0];   // [2, B, N]
    const float* diag     = (const float*)d_in[1];   // [2, N]
    const float* off_diag = (const float*)d_in[2];   // [2, N]
    const int*   pp       = (const int*)d_in[3];     // [N]
    const int*   lp       = (const int*)d_in[4];     // [N]
    const int*   rp       = (const int*)d_in[5];     // [N]
    float* out = (float*)d_out;

    prep_kernel<<<1, N_COLS>>>(pp, lp, rp, diag, off_diag);
    mesh_kernel<<<B_ROWS / ROWS_PER_BLOCK, THREADS>>>(x, out);
}

// round 17
// speedup vs baseline: 1.2361x; 1.2361x over previous
#include <cuda_runtime.h>
#include <cstdint>

// Problem constants (fixed by the reference: x is [2, B, N] fp32)
#define N_COLS 1024
#define B_ROWS 32768
#define THREADS 256
#define ROWS_PER_BLOCK 16
#define CPT 4   // consecutive columns per thread (float4 IO)

// Precomposed per-output-column tables (batch-independent):
//   g_idx[j] = (swz(lp[rp[j]]), swz(lp[pp[rp[j]]]))   (SMEM-swizzled indices)
//   g_w[j]   = (diag_r[k], diag_i[k], off_r[m], off_i[m]) with k=rp[j], m=pp[k]
__device__ int2   g_idx[N_COLS];
__device__ float4 g_w[N_COLS];

// SMEM swizzle on 16B granules of the float2 row buffer:
//   granule G = v>>1  ->  G' = G ^ ((G>>3)&1); within-granule slot (v&1) kept.
// This makes the vectorized STS.128 staging conflict-free per 8-lane phase.
__device__ __host__ __forceinline__ int swz(int v) {
    return ((((v >> 1) ^ ((v >> 4) & 1)) << 1) | (v & 1));
}

__global__ void prep_kernel(const int* __restrict__ pp,
                            const int* __restrict__ lp,
                            const int* __restrict__ rp,
                            const float* __restrict__ diag,      // [2, N]
                            const float* __restrict__ off_diag)  // [2, N]
{
    int j = threadIdx.x;            // 1024 threads, one per output column
    int k = rp[j];
    int m = pp[k];
    g_idx[j] = make_int2(swz(lp[k]), swz(lp[m]));
    g_w[j]   = make_float4(diag[k], diag[N_COLS + k],
                           off_diag[m], off_diag[N_COLS + m]);
}

__global__ void __launch_bounds__(THREADS, 4)
mesh_kernel(const float* __restrict__ x, float* __restrict__ out)
{
    __shared__ float2 s_x[N_COLS];   // 8 KB, swizzled granule layout

    const int t  = threadIdx.x;
    const int c0 = t * CPT;          // 4 consecutive columns per thread

    // Row-invariant table -> registers, once per block (L2-resident reads).
    const int2   id0 = g_idx[c0],     id1 = g_idx[c0 + 1],
                 id2 = g_idx[c0 + 2], id3 = g_idx[c0 + 3];
    const float4 w0  = g_w[c0],       w1  = g_w[c0 + 1],
                 w2  = g_w[c0 + 2],   w3  = g_w[c0 + 3];

    const float* __restrict__ xr = x;                              // [B, N]
    const float* __restrict__ xi = x + (size_t)B_ROWS * N_COLS;
    float* __restrict__ outr = out;
    float* __restrict__ outi = out + (size_t)B_ROWS * N_COLS;

    const int row0 = blockIdx.x * ROWS_PER_BLOCK;

    // Swizzled staging destinations for this thread's two 16B granules.
    const int g1 = swz(c0);          // holds cols c0, c0+1 (interleaved re/im)
    const int g2 = swz(c0 + 2);     // holds cols c0+2, c0+3

    // Software pipeline: prefetch row 0.
    float4 r4 = *(const float4*)(xr + (size_t)row0 * N_COLS + c0);
    float4 i4 = *(const float4*)(xi + (size_t)row0 * N_COLS + c0);

    for (int r = 0; r < ROWS_PER_BLOCK; ++r) {
        const size_t base = (size_t)(row0 + r) * N_COLS;

        // Stage prefetched row into swizzled SMEM (conflict-free STS.128).
        *(float4*)(&s_x[g1]) = make_float4(r4.x, i4.x, r4.y, i4.y);
        *(float4*)(&s_x[g2]) = make_float4(r4.z, i4.z, r4.w, i4.w);
        __syncthreads();

        // Prefetch next row while gathers/compute for this row proceed.
        if (r + 1 < ROWS_PER_BLOCK) {
            const size_t nbase = base + N_COLS;
            r4 = *(const float4*)(xr + nbase + c0);
            i4 = *(const float4*)(xi + nbase + c0);
        }

        // Gathers (indices pre-swizzled), complex MACs.
        const float2 a0 = s_x[id0.x], b0 = s_x[id0.y];
        const float2 a1 = s_x[id1.x], b1 = s_x[id1.y];
        const float2 a2 = s_x[id2.x], b2 = s_x[id2.y];
        const float2 a3 = s_x[id3.x], b3 = s_x[id3.y];

        float4 vr, vi;
        vr.x = a0.x * w0.x - a0.y * w0.y + b0.x * w0.z - b0.y * w0.w;
        vi.x = a0.x * w0.y + a0.y * w0.x + b0.x * w0.w + b0.y * w0.z;
        vr.y = a1.x * w1.x - a1.y * w1.y + b1.x * w1.z - b1.y * w1.w;
        vi.y = a1.x * w1.y + a1.y * w1.x + b1.x * w1.w + b1.y * w1.z;
        vr.z = a2.x * w2.x - a2.y * w2.y + b2.x * w2.z - b2.y * w2.w;
        vi.z = a2.x * w2.y + a2.y * w2.x + b2.x * w2.w + b2.y * w2.z;
        vr.w = a3.x * w3.x - a3.y * w3.y + b3.x * w3.z - b3.y * w3.w;
        vi.w = a3.x * w3.y + a3.y * w3.x + b3.x * w3.w + b3.y * w3.z;

        // Coalesced 16B stores.
        *(float4*)(outr + base + c0) = vr;
        *(float4*)(outi + base + c0) = vi;

        __syncthreads();   // protect s_x before next row's staging
    }
}

extern "C" void kernel_launch(void* const* d_in, const int* in_sizes, int n_in,
                              void* d_out, int out_size)
{
    const float* x        = (const float*)d_in[0];   // [2, B, N]
    const float* diag     = (const float*)d_in[1];   // [2, N]
    const float* off_diag = (const float*)d_in[2];   // [2, N]
    const int*   pp       = (const int*)d_in[3];     // [N]
    const int*   lp       = (const int*)d_in[4];     // [N]
    const int*   rp       = (const int*)d_in[5];     // [N]
    float* out = (float*)d_out;

    prep_kernel<<<1, N_COLS>>>(pp, lp, rp, diag, off_diag);
    mesh_kernel<<<B_ROWS / ROWS_PER_BLOCK, THREADS>>>(x, out);
}